// round 1
// baseline (speedup 1.0000x reference)
#include <cuda_runtime.h>
#include <math.h>

// Problem constants
#define B_ROWS 131072
#define FEAT 256
#define LATD 128
#define NIN 640           // 2*FEAT + LATD
#define HG 32
#define HID 512
#define NE 3

// ---------------------------------------------------------------------------
// Scratch (device globals — no runtime allocation allowed)
// ---------------------------------------------------------------------------
__device__ float g_h1[(size_t)B_ROWS * HID];   // 256 MB
__device__ float g_h2[(size_t)B_ROWS * HID];   // 256 MB
__device__ float g_u[(size_t)B_ROWS * HG];     // 16 MB (gate layer0 pre-activation)
__device__ float g_gate[(size_t)B_ROWS * NE];  // 1.5 MB

// ---------------------------------------------------------------------------
// gate0: u = x @ g0_w^T + g0_b     x = concat(f1,f2,lat)  [B,640] -> [B,32]
// Tile: 256 rows x 32 cols, 256 threads, per-thread 8x4
// ---------------------------------------------------------------------------
__global__ __launch_bounds__(256) void gate0_kernel(
    const float* __restrict__ f1, const float* __restrict__ f2,
    const float* __restrict__ lat,
    const float* __restrict__ w,     // [32, 640]
    const float* __restrict__ bias)  // [32]
{
    __shared__ float As[16][260];   // k-major, 256 rows + pad
    __shared__ float Ws[16][36];    // k-major, 32 cols + pad

    const int tid = threadIdx.x;
    const int tx = tid & 7;        // 0..7  -> 4 output cols each
    const int ty = tid >> 3;       // 0..31 -> 8 rows each
    const int m0 = blockIdx.x * 256;

    float acc[8][4];
#pragma unroll
    for (int i = 0; i < 8; ++i)
#pragma unroll
        for (int j = 0; j < 4; ++j) acc[i][j] = 0.f;

    for (int k0 = 0; k0 < NIN; k0 += 16) {
        // A tile: 256x16 floats = 1024 float4, 4 per thread
#pragma unroll
        for (int r = 0; r < 4; ++r) {
            int idx = r * 256 + tid;
            int m = idx >> 2;
            int kq = (idx & 3) * 4;
            int kg = k0 + kq;
            float4 v;
            if (kg < FEAT)
                v = *reinterpret_cast<const float4*>(&f1[(size_t)(m0 + m) * FEAT + kg]);
            else if (kg < 2 * FEAT)
                v = *reinterpret_cast<const float4*>(&f2[(size_t)(m0 + m) * FEAT + (kg - FEAT)]);
            else
                v = *reinterpret_cast<const float4*>(&lat[(size_t)(m0 + m) * LATD + (kg - 2 * FEAT)]);
            As[kq + 0][m] = v.x; As[kq + 1][m] = v.y;
            As[kq + 2][m] = v.z; As[kq + 3][m] = v.w;
        }
        // W tile: 32x16 = 128 float4
        if (tid < 128) {
            int n = tid >> 2;
            int kq = (tid & 3) * 4;
            float4 v = *reinterpret_cast<const float4*>(&w[(size_t)n * NIN + k0 + kq]);
            Ws[kq + 0][n] = v.x; Ws[kq + 1][n] = v.y;
            Ws[kq + 2][n] = v.z; Ws[kq + 3][n] = v.w;
        }
        __syncthreads();
#pragma unroll
        for (int k = 0; k < 16; ++k) {
            const float4 a0 = *reinterpret_cast<const float4*>(&As[k][ty * 8]);
            const float4 a1 = *reinterpret_cast<const float4*>(&As[k][ty * 8 + 4]);
            const float4 b  = *reinterpret_cast<const float4*>(&Ws[k][tx * 4]);
            float av[8] = {a0.x, a0.y, a0.z, a0.w, a1.x, a1.y, a1.z, a1.w};
            float bv[4] = {b.x, b.y, b.z, b.w};
#pragma unroll
            for (int i = 0; i < 8; ++i)
#pragma unroll
                for (int j = 0; j < 4; ++j)
                    acc[i][j] = fmaf(av[i], bv[j], acc[i][j]);
        }
        __syncthreads();
    }

    float bb[4];
#pragma unroll
    for (int j = 0; j < 4; ++j) bb[j] = bias[tx * 4 + j];
#pragma unroll
    for (int i = 0; i < 8; ++i) {
        int m = m0 + ty * 8 + i;
        float4 o;
        o.x = acc[i][0] + bb[0];
        o.y = acc[i][1] + bb[1];
        o.z = acc[i][2] + bb[2];
        o.w = acc[i][3] + bb[3];
        *reinterpret_cast<float4*>(&g_u[(size_t)m * HG + tx * 4]) = o;
    }
}

// ---------------------------------------------------------------------------
// gate1: elu -> g1 -> elu -> g2 -> softmax -> g_gate + output gate region
// One thread per row, 256 rows per block.
// ---------------------------------------------------------------------------
__global__ __launch_bounds__(256) void gate1_kernel(
    const float* __restrict__ g1w,  // [32,32]
    const float* __restrict__ g1b,  // [32]
    const float* __restrict__ g2w,  // [3,32]
    const float* __restrict__ g2b,  // [3]
    float* __restrict__ out_gate)   // d_out + B*128
{
    __shared__ float us[256][33];
    __shared__ float w1s[32][33];
    __shared__ float b1s[32];
    __shared__ float w2s[3][32];
    __shared__ float b2s[3];

    const int tid = threadIdx.x;
    const int m0 = blockIdx.x * 256;

    for (int idx = tid; idx < 256 * 32; idx += 256) {
        int r = idx >> 5, c = idx & 31;
        us[r][c] = g_u[(size_t)(m0 + r) * HG + c];
    }
    for (int idx = tid; idx < 32 * 32; idx += 256)
        w1s[idx >> 5][idx & 31] = g1w[idx];
    if (tid < 32) b1s[tid] = g1b[tid];
    if (tid < 96) w2s[tid / 32][tid % 32] = g2w[tid];
    if (tid < 3) b2s[tid] = g2b[tid];
    __syncthreads();

    const int m = m0 + tid;

    float eu[32];
#pragma unroll
    for (int k = 0; k < 32; ++k) {
        float x = us[tid][k];
        eu[k] = (x > 0.f) ? x : expm1f(x);
    }

    float ev[32];
#pragma unroll
    for (int j = 0; j < 32; ++j) {
        float v = b1s[j];
#pragma unroll
        for (int k = 0; k < 32; ++k) v = fmaf(eu[k], w1s[j][k], v);
        ev[j] = (v > 0.f) ? v : expm1f(v);
    }

    float s[3];
#pragma unroll
    for (int e = 0; e < 3; ++e) {
        float v = b2s[e];
#pragma unroll
        for (int j = 0; j < 32; ++j) v = fmaf(ev[j], w2s[e][j], v);
        s[e] = v;
    }
    float mx = fmaxf(s[0], fmaxf(s[1], s[2]));
    float p0 = expf(s[0] - mx);
    float p1 = expf(s[1] - mx);
    float p2 = expf(s[2] - mx);
    float inv = 1.f / (p0 + p1 + p2);
    p0 *= inv; p1 *= inv; p2 *= inv;

    g_gate[(size_t)m * 3 + 0] = p0;
    g_gate[(size_t)m * 3 + 1] = p1;
    g_gate[(size_t)m * 3 + 2] = p2;
    out_gate[(size_t)m * 3 + 0] = p0;
    out_gate[(size_t)m * 3 + 1] = p1;
    out_gate[(size_t)m * 3 + 2] = p2;
}

// ---------------------------------------------------------------------------
// blend: Out[m,n] = act( sum_e gate[m,e] * ( (A @ W_e^T)[m,n] + b_e[n] ) )
// Tile: 128 rows x 64 cols x 3 experts, 256 threads, per-thread 8x4x3.
// ASRC: 0 = concat(f1,f2,lat), 1 = g_h1, 2 = g_h2
// ODST: 0 = param pointer, 1 = g_h1, 2 = g_h2
// ---------------------------------------------------------------------------
template <int KDIM, int NOUT, bool RELU, int ASRC, int ODST>
__global__ __launch_bounds__(256) void blend_kernel(
    const float* __restrict__ f1, const float* __restrict__ f2,
    const float* __restrict__ lat,
    const float* __restrict__ W,     // [3, NOUT, KDIM]
    const float* __restrict__ bias,  // [3, NOUT]
    float* __restrict__ outp)
{
    __shared__ float As[16][132];       // k-major A tile (128 rows + pad)
    __shared__ float Ws[3][16][68];     // k-major W tiles (64 cols + pad)

    const int tid = threadIdx.x;
    const int tx = tid & 15;   // 0..15 -> 4 cols each
    const int ty = tid >> 4;   // 0..15 -> 8 rows each
    const int m0 = blockIdx.x * 128;
    const int n0 = blockIdx.y * 64;

    float acc[3][8][4];
#pragma unroll
    for (int e = 0; e < 3; ++e)
#pragma unroll
        for (int i = 0; i < 8; ++i)
#pragma unroll
            for (int j = 0; j < 4; ++j) acc[e][i][j] = 0.f;

    for (int k0 = 0; k0 < KDIM; k0 += 16) {
        // A tile: 128x16 = 512 float4, 2 per thread
#pragma unroll
        for (int r = 0; r < 2; ++r) {
            int idx = r * 256 + tid;
            int m = idx >> 2;
            int kq = (idx & 3) * 4;
            float4 v;
            if (ASRC == 0) {
                int kg = k0 + kq;
                if (kg < FEAT)
                    v = *reinterpret_cast<const float4*>(&f1[(size_t)(m0 + m) * FEAT + kg]);
                else if (kg < 2 * FEAT)
                    v = *reinterpret_cast<const float4*>(&f2[(size_t)(m0 + m) * FEAT + (kg - FEAT)]);
                else
                    v = *reinterpret_cast<const float4*>(&lat[(size_t)(m0 + m) * LATD + (kg - 2 * FEAT)]);
            } else {
                const float* Abuf = (ASRC == 1) ? g_h1 : g_h2;
                v = *reinterpret_cast<const float4*>(&Abuf[(size_t)(m0 + m) * KDIM + k0 + kq]);
            }
            As[kq + 0][m] = v.x; As[kq + 1][m] = v.y;
            As[kq + 2][m] = v.z; As[kq + 3][m] = v.w;
        }
        // W tiles: 3 * 64 * 16 = 768 float4, 3 per thread
#pragma unroll
        for (int r = 0; r < 3; ++r) {
            int idx = r * 256 + tid;          // 0..767
            int e = idx >> 8;
            int rem = idx & 255;
            int n = rem >> 2;
            int kq = (rem & 3) * 4;
            float4 v = *reinterpret_cast<const float4*>(
                &W[((size_t)e * NOUT + n0 + n) * KDIM + k0 + kq]);
            Ws[e][kq + 0][n] = v.x; Ws[e][kq + 1][n] = v.y;
            Ws[e][kq + 2][n] = v.z; Ws[e][kq + 3][n] = v.w;
        }
        __syncthreads();
#pragma unroll
        for (int k = 0; k < 16; ++k) {
            const float4 a0 = *reinterpret_cast<const float4*>(&As[k][ty * 8]);
            const float4 a1 = *reinterpret_cast<const float4*>(&As[k][ty * 8 + 4]);
            float av[8] = {a0.x, a0.y, a0.z, a0.w, a1.x, a1.y, a1.z, a1.w};
#pragma unroll
            for (int e = 0; e < 3; ++e) {
                const float4 b = *reinterpret_cast<const float4*>(&Ws[e][k][tx * 4]);
                float bv[4] = {b.x, b.y, b.z, b.w};
#pragma unroll
                for (int i = 0; i < 8; ++i)
#pragma unroll
                    for (int j = 0; j < 4; ++j)
                        acc[e][i][j] = fmaf(av[i], bv[j], acc[e][i][j]);
            }
        }
        __syncthreads();
    }

    float* O = (ODST == 1) ? g_h1 : ((ODST == 2) ? g_h2 : outp);

    float bb[3][4];
#pragma unroll
    for (int e = 0; e < 3; ++e)
#pragma unroll
        for (int j = 0; j < 4; ++j)
            bb[e][j] = bias[(size_t)e * NOUT + n0 + tx * 4 + j];

#pragma unroll
    for (int i = 0; i < 8; ++i) {
        int m = m0 + ty * 8 + i;
        float ga = g_gate[(size_t)m * 3 + 0];
        float gb = g_gate[(size_t)m * 3 + 1];
        float gc = g_gate[(size_t)m * 3 + 2];
        float o[4];
#pragma unroll
        for (int j = 0; j < 4; ++j) {
            float v = ga * (acc[0][i][j] + bb[0][j])
                    + gb * (acc[1][i][j] + bb[1][j])
                    + gc * (acc[2][i][j] + bb[2][j]);
            if (RELU) v = fmaxf(v, 0.f);
            o[j] = v;
        }
        float4 ov = {o[0], o[1], o[2], o[3]};
        *reinterpret_cast<float4*>(&O[(size_t)m * NOUT + n0 + tx * 4]) = ov;
    }
}

// ---------------------------------------------------------------------------
// Launch
// ---------------------------------------------------------------------------
extern "C" void kernel_launch(void* const* d_in, const int* in_sizes, int n_in,
                              void* d_out, int out_size)
{
    const float* f1  = (const float*)d_in[0];
    const float* f2  = (const float*)d_in[1];
    const float* lat = (const float*)d_in[2];
    const float* g0w = (const float*)d_in[3];
    const float* g0b = (const float*)d_in[4];
    const float* g1w = (const float*)d_in[5];
    const float* g1b = (const float*)d_in[6];
    const float* g2w = (const float*)d_in[7];
    const float* g2b = (const float*)d_in[8];
    const float* W1  = (const float*)d_in[9];
    const float* b1  = (const float*)d_in[10];
    const float* W2  = (const float*)d_in[11];
    const float* b2  = (const float*)d_in[12];
    const float* W3  = (const float*)d_in[13];
    const float* b3  = (const float*)d_in[14];
    const float* W4  = (const float*)d_in[15];
    const float* b4  = (const float*)d_in[16];

    float* out      = (float*)d_out;
    float* gate_out = out + (size_t)B_ROWS * LATD;  // gate region after main output

    // Gate path
    gate0_kernel<<<B_ROWS / 256, 256>>>(f1, f2, lat, g0w, g0b);
    gate1_kernel<<<B_ROWS / 256, 256>>>(g1w, g1b, g2w, g2b, gate_out);

    // Expert-blended MLP
    dim3 grid1(B_ROWS / 128, HID / 64);
    blend_kernel<NIN, HID, true, 0, 1><<<grid1, 256>>>(f1, f2, lat, W1, b1, nullptr);
    blend_kernel<HID, HID, true, 1, 2><<<grid1, 256>>>(nullptr, nullptr, nullptr, W2, b2, nullptr);
    blend_kernel<HID, HID, true, 2, 1><<<grid1, 256>>>(nullptr, nullptr, nullptr, W3, b3, nullptr);

    dim3 grid4(B_ROWS / 128, LATD / 64);
    blend_kernel<HID, LATD, false, 1, 0><<<grid4, 256>>>(nullptr, nullptr, nullptr, W4, b4, out);
}

// round 2
// speedup vs baseline: 2.3414x; 2.3414x over previous
#include <cuda_runtime.h>
#include <cuda_bf16.h>
#include <math.h>

// Problem constants
#define B_ROWS 131072
#define FEAT 256
#define LATD 128
#define NIN 640           // 2*FEAT + LATD
#define HG 32
#define HID 512
#define NE 3

// ---------------------------------------------------------------------------
// Scratch (device globals — no runtime allocation allowed)
// ---------------------------------------------------------------------------
__device__ float g_u[(size_t)B_ROWS * HG];     // gate layer0 pre-activation
__device__ float g_gate[(size_t)B_ROWS * NE];

// hi/lo bf16 planes for activations
__device__ __nv_bfloat16 g_xhi[(size_t)B_ROWS * NIN];
__device__ __nv_bfloat16 g_xlo[(size_t)B_ROWS * NIN];
__device__ __nv_bfloat16 g_h1hi[(size_t)B_ROWS * HID];
__device__ __nv_bfloat16 g_h1lo[(size_t)B_ROWS * HID];
__device__ __nv_bfloat16 g_h2hi[(size_t)B_ROWS * HID];
__device__ __nv_bfloat16 g_h2lo[(size_t)B_ROWS * HID];

// hi/lo bf16 planes for weights
__device__ __nv_bfloat16 g_w1hi[NE * HID * NIN];
__device__ __nv_bfloat16 g_w1lo[NE * HID * NIN];
__device__ __nv_bfloat16 g_w2hi[NE * HID * HID];
__device__ __nv_bfloat16 g_w2lo[NE * HID * HID];
__device__ __nv_bfloat16 g_w3hi[NE * HID * HID];
__device__ __nv_bfloat16 g_w3lo[NE * HID * HID];
__device__ __nv_bfloat16 g_w4hi[NE * LATD * HID];
__device__ __nv_bfloat16 g_w4lo[NE * LATD * HID];

// ---------------------------------------------------------------------------
// helpers
// ---------------------------------------------------------------------------
__device__ __forceinline__ void split_hilo(float v, __nv_bfloat16& h, __nv_bfloat16& l) {
    h = __float2bfloat16_rn(v);
    l = __float2bfloat16_rn(v - __bfloat162float(h));
}

__device__ __forceinline__ void mma16816(float* c, const unsigned* a, const unsigned* b) {
    asm volatile(
        "mma.sync.aligned.m16n8k16.row.col.f32.bf16.bf16.f32 "
        "{%0,%1,%2,%3}, {%4,%5,%6,%7}, {%8,%9}, {%0,%1,%2,%3};\n"
        : "+f"(c[0]), "+f"(c[1]), "+f"(c[2]), "+f"(c[3])
        : "r"(a[0]), "r"(a[1]), "r"(a[2]), "r"(a[3]), "r"(b[0]), "r"(b[1]));
}

// ---------------------------------------------------------------------------
// convert fp32 -> hi/lo bf16 planes (weights)
// ---------------------------------------------------------------------------
__global__ __launch_bounds__(256) void convert_hilo(
    const float* __restrict__ src, __nv_bfloat16* __restrict__ hi,
    __nv_bfloat16* __restrict__ lo, int n4)
{
    int i = blockIdx.x * blockDim.x + threadIdx.x;
    if (i >= n4) return;
    float4 v = reinterpret_cast<const float4*>(src)[i];
    __nv_bfloat16 h0, h1, h2, h3, l0, l1, l2, l3;
    split_hilo(v.x, h0, l0); split_hilo(v.y, h1, l1);
    split_hilo(v.z, h2, l2); split_hilo(v.w, h3, l3);
    __nv_bfloat162* hp = reinterpret_cast<__nv_bfloat162*>(hi) + i * 2;
    __nv_bfloat162* lp = reinterpret_cast<__nv_bfloat162*>(lo) + i * 2;
    hp[0] = __nv_bfloat162{h0, h1}; hp[1] = __nv_bfloat162{h2, h3};
    lp[0] = __nv_bfloat162{l0, l1}; lp[1] = __nv_bfloat162{l2, l3};
}

// ---------------------------------------------------------------------------
// xprep: concat(f1,f2,lat) -> xhi/xlo planes [B,640]
// one thread per 4 elements (boundaries at 256/512 are multiples of 4)
// ---------------------------------------------------------------------------
__global__ __launch_bounds__(256) void xprep_kernel(
    const float* __restrict__ f1, const float* __restrict__ f2,
    const float* __restrict__ lat)
{
    int i = blockIdx.x * blockDim.x + threadIdx.x;   // unit of 4 elems
    int row = i / (NIN / 4);
    int kk = (i % (NIN / 4)) * 4;
    float4 v;
    if (kk < FEAT)
        v = *reinterpret_cast<const float4*>(&f1[(size_t)row * FEAT + kk]);
    else if (kk < 2 * FEAT)
        v = *reinterpret_cast<const float4*>(&f2[(size_t)row * FEAT + kk - FEAT]);
    else
        v = *reinterpret_cast<const float4*>(&lat[(size_t)row * LATD + kk - 2 * FEAT]);
    __nv_bfloat16 h0, h1, h2, h3, l0, l1, l2, l3;
    split_hilo(v.x, h0, l0); split_hilo(v.y, h1, l1);
    split_hilo(v.z, h2, l2); split_hilo(v.w, h3, l3);
    size_t base = (size_t)row * NIN + kk;
    *reinterpret_cast<__nv_bfloat162*>(&g_xhi[base])     = __nv_bfloat162{h0, h1};
    *reinterpret_cast<__nv_bfloat162*>(&g_xhi[base + 2]) = __nv_bfloat162{h2, h3};
    *reinterpret_cast<__nv_bfloat162*>(&g_xlo[base])     = __nv_bfloat162{l0, l1};
    *reinterpret_cast<__nv_bfloat162*>(&g_xlo[base + 2]) = __nv_bfloat162{l2, l3};
}

// ---------------------------------------------------------------------------
// gate0: u = x @ g0_w^T + g0_b   [B,640]->[B,32]  (SIMT fp32, small)
// ---------------------------------------------------------------------------
__global__ __launch_bounds__(256) void gate0_kernel(
    const float* __restrict__ f1, const float* __restrict__ f2,
    const float* __restrict__ lat,
    const float* __restrict__ w, const float* __restrict__ bias)
{
    __shared__ float As[16][260];
    __shared__ float Ws[16][36];

    const int tid = threadIdx.x;
    const int tx = tid & 7;
    const int ty = tid >> 3;
    const int m0 = blockIdx.x * 256;

    float acc[8][4];
#pragma unroll
    for (int i = 0; i < 8; ++i)
#pragma unroll
        for (int j = 0; j < 4; ++j) acc[i][j] = 0.f;

    for (int k0 = 0; k0 < NIN; k0 += 16) {
#pragma unroll
        for (int r = 0; r < 4; ++r) {
            int idx = r * 256 + tid;
            int m = idx >> 2;
            int kq = (idx & 3) * 4;
            int kg = k0 + kq;
            float4 v;
            if (kg < FEAT)
                v = *reinterpret_cast<const float4*>(&f1[(size_t)(m0 + m) * FEAT + kg]);
            else if (kg < 2 * FEAT)
                v = *reinterpret_cast<const float4*>(&f2[(size_t)(m0 + m) * FEAT + (kg - FEAT)]);
            else
                v = *reinterpret_cast<const float4*>(&lat[(size_t)(m0 + m) * LATD + (kg - 2 * FEAT)]);
            As[kq + 0][m] = v.x; As[kq + 1][m] = v.y;
            As[kq + 2][m] = v.z; As[kq + 3][m] = v.w;
        }
        if (tid < 128) {
            int n = tid >> 2;
            int kq = (tid & 3) * 4;
            float4 v = *reinterpret_cast<const float4*>(&w[(size_t)n * NIN + k0 + kq]);
            Ws[kq + 0][n] = v.x; Ws[kq + 1][n] = v.y;
            Ws[kq + 2][n] = v.z; Ws[kq + 3][n] = v.w;
        }
        __syncthreads();
#pragma unroll
        for (int k = 0; k < 16; ++k) {
            const float4 a0 = *reinterpret_cast<const float4*>(&As[k][ty * 8]);
            const float4 a1 = *reinterpret_cast<const float4*>(&As[k][ty * 8 + 4]);
            const float4 b  = *reinterpret_cast<const float4*>(&Ws[k][tx * 4]);
            float av[8] = {a0.x, a0.y, a0.z, a0.w, a1.x, a1.y, a1.z, a1.w};
            float bv[4] = {b.x, b.y, b.z, b.w};
#pragma unroll
            for (int i = 0; i < 8; ++i)
#pragma unroll
                for (int j = 0; j < 4; ++j)
                    acc[i][j] = fmaf(av[i], bv[j], acc[i][j]);
        }
        __syncthreads();
    }

    float bb[4];
#pragma unroll
    for (int j = 0; j < 4; ++j) bb[j] = bias[tx * 4 + j];
#pragma unroll
    for (int i = 0; i < 8; ++i) {
        int m = m0 + ty * 8 + i;
        float4 o;
        o.x = acc[i][0] + bb[0];
        o.y = acc[i][1] + bb[1];
        o.z = acc[i][2] + bb[2];
        o.w = acc[i][3] + bb[3];
        *reinterpret_cast<float4*>(&g_u[(size_t)m * HG + tx * 4]) = o;
    }
}

// ---------------------------------------------------------------------------
// gate1: elu -> g1 -> elu -> g2 -> softmax
// ---------------------------------------------------------------------------
__global__ __launch_bounds__(256) void gate1_kernel(
    const float* __restrict__ g1w, const float* __restrict__ g1b,
    const float* __restrict__ g2w, const float* __restrict__ g2b,
    float* __restrict__ out_gate)
{
    __shared__ float us[256][33];
    __shared__ float w1s[32][33];
    __shared__ float b1s[32];
    __shared__ float w2s[3][32];
    __shared__ float b2s[3];

    const int tid = threadIdx.x;
    const int m0 = blockIdx.x * 256;

    for (int idx = tid; idx < 256 * 32; idx += 256) {
        int r = idx >> 5, c = idx & 31;
        us[r][c] = g_u[(size_t)(m0 + r) * HG + c];
    }
    for (int idx = tid; idx < 32 * 32; idx += 256)
        w1s[idx >> 5][idx & 31] = g1w[idx];
    if (tid < 32) b1s[tid] = g1b[tid];
    if (tid < 96) w2s[tid / 32][tid % 32] = g2w[tid];
    if (tid < 3) b2s[tid] = g2b[tid];
    __syncthreads();

    const int m = m0 + tid;

    float eu[32];
#pragma unroll
    for (int k = 0; k < 32; ++k) {
        float x = us[tid][k];
        eu[k] = (x > 0.f) ? x : expm1f(x);
    }
    float ev[32];
#pragma unroll
    for (int j = 0; j < 32; ++j) {
        float v = b1s[j];
#pragma unroll
        for (int k = 0; k < 32; ++k) v = fmaf(eu[k], w1s[j][k], v);
        ev[j] = (v > 0.f) ? v : expm1f(v);
    }
    float s[3];
#pragma unroll
    for (int e = 0; e < 3; ++e) {
        float v = b2s[e];
#pragma unroll
        for (int j = 0; j < 32; ++j) v = fmaf(ev[j], w2s[e][j], v);
        s[e] = v;
    }
    float mx = fmaxf(s[0], fmaxf(s[1], s[2]));
    float p0 = expf(s[0] - mx);
    float p1 = expf(s[1] - mx);
    float p2 = expf(s[2] - mx);
    float inv = 1.f / (p0 + p1 + p2);
    p0 *= inv; p1 *= inv; p2 *= inv;

    g_gate[(size_t)m * 3 + 0] = p0;
    g_gate[(size_t)m * 3 + 1] = p1;
    g_gate[(size_t)m * 3 + 2] = p2;
    out_gate[(size_t)m * 3 + 0] = p0;
    out_gate[(size_t)m * 3 + 1] = p1;
    out_gate[(size_t)m * 3 + 2] = p2;
}

// ---------------------------------------------------------------------------
// blend_mma: Out[m,n] = act( sum_e gate[m,e] * ((A @ W_e^T)[m,n] + b_e[n]) )
// bf16 2-term compensated mma (hi*hi + hi*lo + lo*hi), fp32 accumulate.
// Block tile: M=128 x N=64 x E=3, 8 warps (warp tile 32x32 per expert).
// ---------------------------------------------------------------------------
template <int KDIM, int NOUT, bool RELU, bool FP32OUT>
__global__ __launch_bounds__(256) void blend_mma(
    const __nv_bfloat16* __restrict__ Ahi, const __nv_bfloat16* __restrict__ Alo,
    const __nv_bfloat16* __restrict__ Whi, const __nv_bfloat16* __restrict__ Wlo,
    const float* __restrict__ bias,
    __nv_bfloat16* __restrict__ Ohi, __nv_bfloat16* __restrict__ Olo,
    float* __restrict__ Ofp)
{
    __shared__ __nv_bfloat16 sA[2][128 * 36];   // [hi/lo][row*36 + k]
    __shared__ __nv_bfloat16 sW[2][192 * 36];   // [hi/lo][(e*64+n)*36 + k]

    const int tid = threadIdx.x;
    const int m0 = blockIdx.y * 128;
    const int n0 = blockIdx.x * 64;
    const int w = tid >> 5, lane = tid & 31;
    const int wm = w & 3, wn = w >> 2;          // warp: 4 along M, 2 along N
    const int g = lane >> 2, t = lane & 3;

    float acc[3][2][4][4];
#pragma unroll
    for (int e = 0; e < 3; ++e)
#pragma unroll
        for (int mt = 0; mt < 2; ++mt)
#pragma unroll
            for (int nt = 0; nt < 4; ++nt)
#pragma unroll
                for (int c = 0; c < 4; ++c) acc[e][mt][nt][c] = 0.f;

    for (int k0 = 0; k0 < KDIM; k0 += 32) {
        __syncthreads();
        // A tile: 128 x 32, hi+lo
#pragma unroll
        for (int i = 0; i < 4; ++i) {
            int u = tid + i * 256;                 // 0..1023
            int row = u >> 3, kk = (u & 7) * 4;
            size_t ga = (size_t)(m0 + row) * KDIM + k0 + kk;
            int sa = row * 36 + kk;
            *reinterpret_cast<uint2*>(&sA[0][sa]) = *reinterpret_cast<const uint2*>(&Ahi[ga]);
            *reinterpret_cast<uint2*>(&sA[1][sa]) = *reinterpret_cast<const uint2*>(&Alo[ga]);
        }
        // W tiles: 3 x 64 x 32, hi+lo
#pragma unroll
        for (int i = 0; i < 6; ++i) {
            int u = tid + i * 256;                 // 0..1535
            int e = u >> 9, rem = u & 511;
            int n = rem >> 3, kk = (rem & 7) * 4;
            size_t ga = ((size_t)e * NOUT + n0 + n) * KDIM + k0 + kk;
            int sw = (e * 64 + n) * 36 + kk;
            *reinterpret_cast<uint2*>(&sW[0][sw]) = *reinterpret_cast<const uint2*>(&Whi[ga]);
            *reinterpret_cast<uint2*>(&sW[1][sw]) = *reinterpret_cast<const uint2*>(&Wlo[ga]);
        }
        __syncthreads();

#pragma unroll
        for (int ks = 0; ks < 32; ks += 16) {
            unsigned ah[2][4], al[2][4];
#pragma unroll
            for (int mt = 0; mt < 2; ++mt) {
                int r0 = (wm * 32 + mt * 16 + g) * 36 + ks + t * 2;
                int r1 = r0 + 8 * 36;
                ah[mt][0] = *reinterpret_cast<const unsigned*>(&sA[0][r0]);
                ah[mt][1] = *reinterpret_cast<const unsigned*>(&sA[0][r1]);
                ah[mt][2] = *reinterpret_cast<const unsigned*>(&sA[0][r0 + 8]);
                ah[mt][3] = *reinterpret_cast<const unsigned*>(&sA[0][r1 + 8]);
                al[mt][0] = *reinterpret_cast<const unsigned*>(&sA[1][r0]);
                al[mt][1] = *reinterpret_cast<const unsigned*>(&sA[1][r1]);
                al[mt][2] = *reinterpret_cast<const unsigned*>(&sA[1][r0 + 8]);
                al[mt][3] = *reinterpret_cast<const unsigned*>(&sA[1][r1 + 8]);
            }
#pragma unroll
            for (int e = 0; e < 3; ++e) {
                unsigned bh[4][2], bl[4][2];
#pragma unroll
                for (int nt = 0; nt < 4; ++nt) {
                    int c0 = (e * 64 + wn * 32 + nt * 8 + g) * 36 + ks + t * 2;
                    bh[nt][0] = *reinterpret_cast<const unsigned*>(&sW[0][c0]);
                    bh[nt][1] = *reinterpret_cast<const unsigned*>(&sW[0][c0 + 8]);
                    bl[nt][0] = *reinterpret_cast<const unsigned*>(&sW[1][c0]);
                    bl[nt][1] = *reinterpret_cast<const unsigned*>(&sW[1][c0 + 8]);
                }
#pragma unroll
                for (int mt = 0; mt < 2; ++mt)
#pragma unroll
                    for (int nt = 0; nt < 4; ++nt) {
                        mma16816(acc[e][mt][nt], ah[mt], bh[nt]);
                        mma16816(acc[e][mt][nt], ah[mt], bl[nt]);
                        mma16816(acc[e][mt][nt], al[mt], bh[nt]);
                    }
            }
        }
    }

    // epilogue
    float bb[3][4][2];
#pragma unroll
    for (int e = 0; e < 3; ++e)
#pragma unroll
        for (int nt = 0; nt < 4; ++nt) {
            int n = n0 + wn * 32 + nt * 8 + t * 2;
            bb[e][nt][0] = bias[e * NOUT + n];
            bb[e][nt][1] = bias[e * NOUT + n + 1];
        }

#pragma unroll
    for (int mt = 0; mt < 2; ++mt)
#pragma unroll
        for (int h = 0; h < 2; ++h) {
            int m = m0 + wm * 32 + mt * 16 + g + h * 8;
            float ga = g_gate[(size_t)m * 3 + 0];
            float gb = g_gate[(size_t)m * 3 + 1];
            float gc = g_gate[(size_t)m * 3 + 2];
#pragma unroll
            for (int nt = 0; nt < 4; ++nt) {
                int n = n0 + wn * 32 + nt * 8 + t * 2;
                float v0 = ga * (acc[0][mt][nt][h * 2 + 0] + bb[0][nt][0])
                         + gb * (acc[1][mt][nt][h * 2 + 0] + bb[1][nt][0])
                         + gc * (acc[2][mt][nt][h * 2 + 0] + bb[2][nt][0]);
                float v1 = ga * (acc[0][mt][nt][h * 2 + 1] + bb[0][nt][1])
                         + gb * (acc[1][mt][nt][h * 2 + 1] + bb[1][nt][1])
                         + gc * (acc[2][mt][nt][h * 2 + 1] + bb[2][nt][1]);
                if (RELU) { v0 = fmaxf(v0, 0.f); v1 = fmaxf(v1, 0.f); }
                if (FP32OUT) {
                    float2 o = {v0, v1};
                    *reinterpret_cast<float2*>(&Ofp[(size_t)m * NOUT + n]) = o;
                } else {
                    __nv_bfloat16 h0, h1, l0, l1;
                    split_hilo(v0, h0, l0);
                    split_hilo(v1, h1, l1);
                    *reinterpret_cast<__nv_bfloat162*>(&Ohi[(size_t)m * NOUT + n]) = __nv_bfloat162{h0, h1};
                    *reinterpret_cast<__nv_bfloat162*>(&Olo[(size_t)m * NOUT + n]) = __nv_bfloat162{l0, l1};
                }
            }
        }
}

// ---------------------------------------------------------------------------
// Launch
// ---------------------------------------------------------------------------
extern "C" void kernel_launch(void* const* d_in, const int* in_sizes, int n_in,
                              void* d_out, int out_size)
{
    const float* f1  = (const float*)d_in[0];
    const float* f2  = (const float*)d_in[1];
    const float* lat = (const float*)d_in[2];
    const float* g0w = (const float*)d_in[3];
    const float* g0b = (const float*)d_in[4];
    const float* g1w = (const float*)d_in[5];
    const float* g1b = (const float*)d_in[6];
    const float* g2w = (const float*)d_in[7];
    const float* g2b = (const float*)d_in[8];
    const float* W1  = (const float*)d_in[9];
    const float* b1  = (const float*)d_in[10];
    const float* W2  = (const float*)d_in[11];
    const float* b2  = (const float*)d_in[12];
    const float* W3  = (const float*)d_in[13];
    const float* b3  = (const float*)d_in[14];
    const float* W4  = (const float*)d_in[15];
    const float* b4  = (const float*)d_in[16];

    float* out      = (float*)d_out;
    float* gate_out = out + (size_t)B_ROWS * LATD;

    // resolve device-global scratch addresses (host side, not captured ops)
    __nv_bfloat16 *w1hi, *w1lo, *w2hi, *w2lo, *w3hi, *w3lo, *w4hi, *w4lo;
    __nv_bfloat16 *xhi, *xlo, *h1hi, *h1lo, *h2hi, *h2lo;
    cudaGetSymbolAddress((void**)&w1hi, g_w1hi); cudaGetSymbolAddress((void**)&w1lo, g_w1lo);
    cudaGetSymbolAddress((void**)&w2hi, g_w2hi); cudaGetSymbolAddress((void**)&w2lo, g_w2lo);
    cudaGetSymbolAddress((void**)&w3hi, g_w3hi); cudaGetSymbolAddress((void**)&w3lo, g_w3lo);
    cudaGetSymbolAddress((void**)&w4hi, g_w4hi); cudaGetSymbolAddress((void**)&w4lo, g_w4lo);
    cudaGetSymbolAddress((void**)&xhi,  g_xhi);  cudaGetSymbolAddress((void**)&xlo,  g_xlo);
    cudaGetSymbolAddress((void**)&h1hi, g_h1hi); cudaGetSymbolAddress((void**)&h1lo, g_h1lo);
    cudaGetSymbolAddress((void**)&h2hi, g_h2hi); cudaGetSymbolAddress((void**)&h2lo, g_h2lo);

    // weight + input conversion
    {
        int n4 = NE * HID * NIN / 4;
        convert_hilo<<<(n4 + 255) / 256, 256>>>(W1, w1hi, w1lo, n4);
        n4 = NE * HID * HID / 4;
        convert_hilo<<<(n4 + 255) / 256, 256>>>(W2, w2hi, w2lo, n4);
        convert_hilo<<<(n4 + 255) / 256, 256>>>(W3, w3hi, w3lo, n4);
        n4 = NE * LATD * HID / 4;
        convert_hilo<<<(n4 + 255) / 256, 256>>>(W4, w4hi, w4lo, n4);
        int nx = B_ROWS * (NIN / 4);
        xprep_kernel<<<nx / 256, 256>>>(f1, f2, lat);
    }

    // gate path
    gate0_kernel<<<B_ROWS / 256, 256>>>(f1, f2, lat, g0w, g0b);
    gate1_kernel<<<B_ROWS / 256, 256>>>(g1w, g1b, g2w, g2b, gate_out);

    // expert-blended MLP (grid: x = n-blocks (fast) for L2 reuse of A slabs)
    dim3 grid1(HID / 64, B_ROWS / 128);
    blend_mma<NIN, HID, true, false><<<grid1, 256>>>(xhi, xlo, w1hi, w1lo, b1, h1hi, h1lo, nullptr);
    blend_mma<HID, HID, true, false><<<grid1, 256>>>(h1hi, h1lo, w2hi, w2lo, b2, h2hi, h2lo, nullptr);
    blend_mma<HID, HID, true, false><<<grid1, 256>>>(h2hi, h2lo, w3hi, w3lo, b3, h1hi, h1lo, nullptr);

    dim3 grid4(LATD / 64, B_ROWS / 128);
    blend_mma<HID, LATD, false, true><<<grid4, 256>>>(h1hi, h1lo, w4hi, w4lo, b4, nullptr, nullptr, out);
}

// round 5
// speedup vs baseline: 3.1856x; 1.3606x over previous
#include <cuda_runtime.h>
#include <cuda_bf16.h>
#include <math.h>
#include <stdint.h>

// Problem constants
#define B_ROWS 131072
#define FEAT 256
#define LATD 128
#define NIN 640           // 2*FEAT + LATD
#define HG 32
#define HID 512
#define NE 3

// ---------------------------------------------------------------------------
// Scratch (device globals — no runtime allocation allowed)
// ---------------------------------------------------------------------------
__device__ float g_u[(size_t)B_ROWS * HG];
__device__ float g_gate[(size_t)B_ROWS * NE];

__device__ __nv_bfloat16 g_xhi[(size_t)B_ROWS * NIN];
__device__ __nv_bfloat16 g_xlo[(size_t)B_ROWS * NIN];
__device__ __nv_bfloat16 g_h1hi[(size_t)B_ROWS * HID];
__device__ __nv_bfloat16 g_h1lo[(size_t)B_ROWS * HID];
__device__ __nv_bfloat16 g_h2hi[(size_t)B_ROWS * HID];
__device__ __nv_bfloat16 g_h2lo[(size_t)B_ROWS * HID];

__device__ __nv_bfloat16 g_w1hi[NE * HID * NIN];
__device__ __nv_bfloat16 g_w1lo[NE * HID * NIN];
__device__ __nv_bfloat16 g_w2hi[NE * HID * HID];
__device__ __nv_bfloat16 g_w2lo[NE * HID * HID];
__device__ __nv_bfloat16 g_w3hi[NE * HID * HID];
__device__ __nv_bfloat16 g_w3lo[NE * HID * HID];
__device__ __nv_bfloat16 g_w4hi[NE * LATD * HID];
__device__ __nv_bfloat16 g_w4lo[NE * LATD * HID];

// ---------------------------------------------------------------------------
// helpers
// ---------------------------------------------------------------------------
__device__ __forceinline__ uint32_t smem_u32(const void* p) {
    uint32_t a;
    asm("{ .reg .u64 t; cvta.to.shared.u64 t, %1; cvt.u32.u64 %0, t; }" : "=r"(a) : "l"(p));
    return a;
}

#define CP_ASYNC16(dst, src) \
    asm volatile("cp.async.cg.shared.global [%0], [%1], 16;" :: "r"(dst), "l"(src))
#define CP_COMMIT() asm volatile("cp.async.commit_group;" ::: "memory")
#define CP_WAIT0()  asm volatile("cp.async.wait_group 0;" ::: "memory")
#define CP_WAIT1()  asm volatile("cp.async.wait_group 1;" ::: "memory")

__device__ __forceinline__ void split_hilo(float v, __nv_bfloat16& h, __nv_bfloat16& l) {
    h = __float2bfloat16_rn(v);
    l = __float2bfloat16_rn(v - __bfloat162float(h));
}

__device__ __forceinline__ void mma16816(float* c, const unsigned* a, const unsigned* b) {
    asm volatile(
        "mma.sync.aligned.m16n8k16.row.col.f32.bf16.bf16.f32 "
        "{%0,%1,%2,%3}, {%4,%5,%6,%7}, {%8,%9}, {%0,%1,%2,%3};\n"
        : "+f"(c[0]), "+f"(c[1]), "+f"(c[2]), "+f"(c[3])
        : "r"(a[0]), "r"(a[1]), "r"(a[2]), "r"(a[3]), "r"(b[0]), "r"(b[1]));
}

__device__ __forceinline__ unsigned lds32(const __nv_bfloat16* p) {
    return *reinterpret_cast<const unsigned*>(p);
}

// ---------------------------------------------------------------------------
// prep kernels (unchanged; proven)
// ---------------------------------------------------------------------------
__global__ __launch_bounds__(256) void convert_hilo(
    const float* __restrict__ src, __nv_bfloat16* __restrict__ hi,
    __nv_bfloat16* __restrict__ lo, int n4)
{
    int i = blockIdx.x * blockDim.x + threadIdx.x;
    if (i >= n4) return;
    float4 v = reinterpret_cast<const float4*>(src)[i];
    __nv_bfloat16 h0, h1, h2, h3, l0, l1, l2, l3;
    split_hilo(v.x, h0, l0); split_hilo(v.y, h1, l1);
    split_hilo(v.z, h2, l2); split_hilo(v.w, h3, l3);
    __nv_bfloat162* hp = reinterpret_cast<__nv_bfloat162*>(hi) + i * 2;
    __nv_bfloat162* lp = reinterpret_cast<__nv_bfloat162*>(lo) + i * 2;
    hp[0] = __nv_bfloat162{h0, h1}; hp[1] = __nv_bfloat162{h2, h3};
    lp[0] = __nv_bfloat162{l0, l1}; lp[1] = __nv_bfloat162{l2, l3};
}

__global__ __launch_bounds__(256) void xprep_kernel(
    const float* __restrict__ f1, const float* __restrict__ f2,
    const float* __restrict__ lat)
{
    int i = blockIdx.x * blockDim.x + threadIdx.x;
    int row = i / (NIN / 4);
    int kk = (i % (NIN / 4)) * 4;
    float4 v;
    if (kk < FEAT)
        v = *reinterpret_cast<const float4*>(&f1[(size_t)row * FEAT + kk]);
    else if (kk < 2 * FEAT)
        v = *reinterpret_cast<const float4*>(&f2[(size_t)row * FEAT + kk - FEAT]);
    else
        v = *reinterpret_cast<const float4*>(&lat[(size_t)row * LATD + kk - 2 * FEAT]);
    __nv_bfloat16 h0, h1, h2, h3, l0, l1, l2, l3;
    split_hilo(v.x, h0, l0); split_hilo(v.y, h1, l1);
    split_hilo(v.z, h2, l2); split_hilo(v.w, h3, l3);
    size_t base = (size_t)row * NIN + kk;
    *reinterpret_cast<__nv_bfloat162*>(&g_xhi[base])     = __nv_bfloat162{h0, h1};
    *reinterpret_cast<__nv_bfloat162*>(&g_xhi[base + 2]) = __nv_bfloat162{h2, h3};
    *reinterpret_cast<__nv_bfloat162*>(&g_xlo[base])     = __nv_bfloat162{l0, l1};
    *reinterpret_cast<__nv_bfloat162*>(&g_xlo[base + 2]) = __nv_bfloat162{l2, l3};
}

__global__ __launch_bounds__(256) void gate0_kernel(
    const float* __restrict__ f1, const float* __restrict__ f2,
    const float* __restrict__ lat,
    const float* __restrict__ w, const float* __restrict__ bias)
{
    __shared__ float As[16][260];
    __shared__ float Ws[16][36];

    const int tid = threadIdx.x;
    const int tx = tid & 7;
    const int ty = tid >> 3;
    const int m0 = blockIdx.x * 256;

    float acc[8][4];
#pragma unroll
    for (int i = 0; i < 8; ++i)
#pragma unroll
        for (int j = 0; j < 4; ++j) acc[i][j] = 0.f;

    for (int k0 = 0; k0 < NIN; k0 += 16) {
#pragma unroll
        for (int r = 0; r < 4; ++r) {
            int idx = r * 256 + tid;
            int m = idx >> 2;
            int kq = (idx & 3) * 4;
            int kg = k0 + kq;
            float4 v;
            if (kg < FEAT)
                v = *reinterpret_cast<const float4*>(&f1[(size_t)(m0 + m) * FEAT + kg]);
            else if (kg < 2 * FEAT)
                v = *reinterpret_cast<const float4*>(&f2[(size_t)(m0 + m) * FEAT + (kg - FEAT)]);
            else
                v = *reinterpret_cast<const float4*>(&lat[(size_t)(m0 + m) * LATD + (kg - 2 * FEAT)]);
            As[kq + 0][m] = v.x; As[kq + 1][m] = v.y;
            As[kq + 2][m] = v.z; As[kq + 3][m] = v.w;
        }
        if (tid < 128) {
            int n = tid >> 2;
            int kq = (tid & 3) * 4;
            float4 v = *reinterpret_cast<const float4*>(&w[(size_t)n * NIN + k0 + kq]);
            Ws[kq + 0][n] = v.x; Ws[kq + 1][n] = v.y;
            Ws[kq + 2][n] = v.z; Ws[kq + 3][n] = v.w;
        }
        __syncthreads();
#pragma unroll
        for (int k = 0; k < 16; ++k) {
            const float4 a0 = *reinterpret_cast<const float4*>(&As[k][ty * 8]);
            const float4 a1 = *reinterpret_cast<const float4*>(&As[k][ty * 8 + 4]);
            const float4 b  = *reinterpret_cast<const float4*>(&Ws[k][tx * 4]);
            float av[8] = {a0.x, a0.y, a0.z, a0.w, a1.x, a1.y, a1.z, a1.w};
            float bv[4] = {b.x, b.y, b.z, b.w};
#pragma unroll
            for (int i = 0; i < 8; ++i)
#pragma unroll
                for (int j = 0; j < 4; ++j)
                    acc[i][j] = fmaf(av[i], bv[j], acc[i][j]);
        }
        __syncthreads();
    }

    float bb[4];
#pragma unroll
    for (int j = 0; j < 4; ++j) bb[j] = bias[tx * 4 + j];
#pragma unroll
    for (int i = 0; i < 8; ++i) {
        int m = m0 + ty * 8 + i;
        float4 o;
        o.x = acc[i][0] + bb[0];
        o.y = acc[i][1] + bb[1];
        o.z = acc[i][2] + bb[2];
        o.w = acc[i][3] + bb[3];
        *reinterpret_cast<float4*>(&g_u[(size_t)m * HG + tx * 4]) = o;
    }
}

__global__ __launch_bounds__(256) void gate1_kernel(
    const float* __restrict__ g1w, const float* __restrict__ g1b,
    const float* __restrict__ g2w, const float* __restrict__ g2b,
    float* __restrict__ out_gate)
{
    __shared__ float us[256][33];
    __shared__ float w1s[32][33];
    __shared__ float b1s[32];
    __shared__ float w2s[3][32];
    __shared__ float b2s[3];

    const int tid = threadIdx.x;
    const int m0 = blockIdx.x * 256;

    for (int idx = tid; idx < 256 * 32; idx += 256) {
        int r = idx >> 5, c = idx & 31;
        us[r][c] = g_u[(size_t)(m0 + r) * HG + c];
    }
    for (int idx = tid; idx < 32 * 32; idx += 256)
        w1s[idx >> 5][idx & 31] = g1w[idx];
    if (tid < 32) b1s[tid] = g1b[tid];
    if (tid < 96) w2s[tid / 32][tid % 32] = g2w[tid];
    if (tid < 3) b2s[tid] = g2b[tid];
    __syncthreads();

    const int m = m0 + tid;

    float eu[32];
#pragma unroll
    for (int k = 0; k < 32; ++k) {
        float x = us[tid][k];
        eu[k] = (x > 0.f) ? x : expm1f(x);
    }
    float ev[32];
#pragma unroll
    for (int j = 0; j < 32; ++j) {
        float v = b1s[j];
#pragma unroll
        for (int k = 0; k < 32; ++k) v = fmaf(eu[k], w1s[j][k], v);
        ev[j] = (v > 0.f) ? v : expm1f(v);
    }
    float s[3];
#pragma unroll
    for (int e = 0; e < 3; ++e) {
        float v = b2s[e];
#pragma unroll
        for (int j = 0; j < 32; ++j) v = fmaf(ev[j], w2s[e][j], v);
        s[e] = v;
    }
    float mx = fmaxf(s[0], fmaxf(s[1], s[2]));
    float p0 = expf(s[0] - mx);
    float p1 = expf(s[1] - mx);
    float p2 = expf(s[2] - mx);
    float inv = 1.f / (p0 + p1 + p2);
    p0 *= inv; p1 *= inv; p2 *= inv;

    g_gate[(size_t)m * 3 + 0] = p0;
    g_gate[(size_t)m * 3 + 1] = p1;
    g_gate[(size_t)m * 3 + 2] = p2;
    out_gate[(size_t)m * 3 + 0] = p0;
    out_gate[(size_t)m * 3 + 1] = p1;
    out_gate[(size_t)m * 3 + 2] = p2;
}

// ---------------------------------------------------------------------------
// blend_mma v2: cp.async 2-stage pipelined, K-chunk = 64.
// Out[m,n] = act( sum_e gate[m,e] * ((A @ W_e^T)[m,n] + b_e[n]) )
// bf16 3-term compensated mma (hh + hl + lh), fp32 accumulate.
// Block tile: M=128 x N=64 x E=3, 8 warps (warp tile 32x32 per expert).
//
// smem per stage (bf16 units, row stride 72 = 64k + 8 pad):
//   A hi 128*72 | A lo 128*72 | W hi 192*72 | W lo 192*72   = 46080 units (92160B)
// ---------------------------------------------------------------------------
#define ASTRIDE 72
#define AROWS 128
#define WROWS 192
#define STAGE_U (2 * (AROWS + WROWS) * ASTRIDE)   // 46080 bf16 units

template <int KDIM, int NOUT>
__device__ __forceinline__ void prefetch_chunk(
    __nv_bfloat16* sm, int stage, int k0, int m0, int n0,
    const __nv_bfloat16* __restrict__ Ahi, const __nv_bfloat16* __restrict__ Alo,
    const __nv_bfloat16* __restrict__ Whi, const __nv_bfloat16* __restrict__ Wlo)
{
    const int tid = threadIdx.x;
    const uint32_t base = smem_u32(sm) + (uint32_t)stage * STAGE_U * 2;
    // A: 2 planes * 128 rows * 8 chunks = 2048 ; W: 2 planes * 192 rows * 8 = 3072
#pragma unroll
    for (int it = 0; it < 20; ++it) {
        int i = tid + it * 256;               // 0..5119
        uint32_t dst;
        const __nv_bfloat16* src;
        if (i < 2048) {
            int plane = i >> 10;              // 0 hi, 1 lo
            int idx = i & 1023;
            int row = idx >> 3, c = idx & 7;
            const __nv_bfloat16* Ap = plane ? Alo : Ahi;
            src = Ap + (size_t)(m0 + row) * KDIM + k0 + c * 8;
            dst = base + (uint32_t)(plane * AROWS * ASTRIDE + row * ASTRIDE + c * 8) * 2;
        } else {
            int j = i - 2048;                 // 0..3071
            int plane = j / 1536;
            int idx = j - plane * 1536;
            int r = idx >> 3, c = idx & 7;    // r in [0,192)
            int e = r >> 6, n = r & 63;
            const __nv_bfloat16* Wp = plane ? Wlo : Whi;
            src = Wp + ((size_t)e * NOUT + n0 + n) * KDIM + k0 + c * 8;
            dst = base + (uint32_t)(2 * AROWS * ASTRIDE + plane * WROWS * ASTRIDE +
                                    r * ASTRIDE + c * 8) * 2;
        }
        CP_ASYNC16(dst, src);
    }
}

template <int KDIM, int NOUT, bool RELU, bool FP32OUT>
__global__ __launch_bounds__(256, 1) void blend_mma(
    const __nv_bfloat16* __restrict__ Ahi, const __nv_bfloat16* __restrict__ Alo,
    const __nv_bfloat16* __restrict__ Whi, const __nv_bfloat16* __restrict__ Wlo,
    const float* __restrict__ bias,
    __nv_bfloat16* __restrict__ Ohi, __nv_bfloat16* __restrict__ Olo,
    float* __restrict__ Ofp)
{
    extern __shared__ __nv_bfloat16 smbuf[];

    const int tid = threadIdx.x;
    const int m0 = blockIdx.y * 128;
    const int n0 = blockIdx.x * 64;
    const int w = tid >> 5, lane = tid & 31;
    const int wm = w & 3, wn = w >> 2;          // warps: 4 along M, 2 along N
    const int g = lane >> 2, t = lane & 3;

    float acc[3][2][4][4];
#pragma unroll
    for (int e = 0; e < 3; ++e)
#pragma unroll
        for (int mt = 0; mt < 2; ++mt)
#pragma unroll
            for (int nt = 0; nt < 4; ++nt)
#pragma unroll
                for (int c = 0; c < 4; ++c) acc[e][mt][nt][c] = 0.f;

    constexpr int NCH = KDIM / 64;

    prefetch_chunk<KDIM, NOUT>(smbuf, 0, 0, m0, n0, Ahi, Alo, Whi, Wlo);
    CP_COMMIT();

    for (int ch = 0; ch < NCH; ++ch) {
        const int cur = ch & 1;
        if (ch + 1 < NCH) {
            prefetch_chunk<KDIM, NOUT>(smbuf, cur ^ 1, (ch + 1) * 64, m0, n0,
                                       Ahi, Alo, Whi, Wlo);
            CP_COMMIT();
            CP_WAIT1();
        } else {
            CP_WAIT0();
        }
        __syncthreads();

        const __nv_bfloat16* sAh = smbuf + cur * STAGE_U;
        const __nv_bfloat16* sAl = sAh + AROWS * ASTRIDE;
        const __nv_bfloat16* sWh = sAl + AROWS * ASTRIDE;
        const __nv_bfloat16* sWl = sWh + WROWS * ASTRIDE;

#pragma unroll
        for (int ks = 0; ks < 64; ks += 16) {
            unsigned ah[2][4], al[2][4];
#pragma unroll
            for (int mt = 0; mt < 2; ++mt) {
                int r0 = (wm * 32 + mt * 16 + g) * ASTRIDE + ks + t * 2;
                int r1 = r0 + 8 * ASTRIDE;
                ah[mt][0] = lds32(sAh + r0);
                ah[mt][1] = lds32(sAh + r1);
                ah[mt][2] = lds32(sAh + r0 + 8);
                ah[mt][3] = lds32(sAh + r1 + 8);
                al[mt][0] = lds32(sAl + r0);
                al[mt][1] = lds32(sAl + r1);
                al[mt][2] = lds32(sAl + r0 + 8);
                al[mt][3] = lds32(sAl + r1 + 8);
            }
#pragma unroll
            for (int e = 0; e < 3; ++e) {
                unsigned bh[4][2], bl[4][2];
#pragma unroll
                for (int nt = 0; nt < 4; ++nt) {
                    int c0 = (e * 64 + wn * 32 + nt * 8 + g) * ASTRIDE + ks + t * 2;
                    bh[nt][0] = lds32(sWh + c0);
                    bh[nt][1] = lds32(sWh + c0 + 8);
                    bl[nt][0] = lds32(sWl + c0);
                    bl[nt][1] = lds32(sWl + c0 + 8);
                }
#pragma unroll
                for (int mt = 0; mt < 2; ++mt)
#pragma unroll
                    for (int nt = 0; nt < 4; ++nt) {
                        mma16816(acc[e][mt][nt], ah[mt], bh[nt]);
                        mma16816(acc[e][mt][nt], ah[mt], bl[nt]);
                        mma16816(acc[e][mt][nt], al[mt], bh[nt]);
                    }
            }
        }
        __syncthreads();
    }

    // ---------------- epilogue ----------------
    float bb[3][4][2];
#pragma unroll
    for (int e = 0; e < 3; ++e)
#pragma unroll
        for (int nt = 0; nt < 4; ++nt) {
            int n = n0 + wn * 32 + nt * 8 + t * 2;
            bb[e][nt][0] = bias[e * NOUT + n];
            bb[e][nt][1] = bias[e * NOUT + n + 1];
        }

#pragma unroll
    for (int mt = 0; mt < 2; ++mt)
#pragma unroll
        for (int h = 0; h < 2; ++h) {
            int m = m0 + wm * 32 + mt * 16 + g + h * 8;
            float ga = g_gate[(size_t)m * 3 + 0];
            float gb = g_gate[(size_t)m * 3 + 1];
            float gc = g_gate[(size_t)m * 3 + 2];
#pragma unroll
            for (int nt = 0; nt < 4; ++nt) {
                int n = n0 + wn * 32 + nt * 8 + t * 2;
                float v0 = ga * (acc[0][mt][nt][h * 2 + 0] + bb[0][nt][0])
                         + gb * (acc[1][mt][nt][h * 2 + 0] + bb[1][nt][0])
                         + gc * (acc[2][mt][nt][h * 2 + 0] + bb[2][nt][0]);
                float v1 = ga * (acc[0][mt][nt][h * 2 + 1] + bb[0][nt][1])
                         + gb * (acc[1][mt][nt][h * 2 + 1] + bb[1][nt][1])
                         + gc * (acc[2][mt][nt][h * 2 + 1] + bb[2][nt][1]);
                if (RELU) { v0 = fmaxf(v0, 0.f); v1 = fmaxf(v1, 0.f); }
                if (FP32OUT) {
                    float2 o = {v0, v1};
                    *reinterpret_cast<float2*>(&Ofp[(size_t)m * NOUT + n]) = o;
                } else {
                    __nv_bfloat16 h0, h1, l0, l1;
                    split_hilo(v0, h0, l0);
                    split_hilo(v1, h1, l1);
                    *reinterpret_cast<__nv_bfloat162*>(&Ohi[(size_t)m * NOUT + n]) = __nv_bfloat162{h0, h1};
                    *reinterpret_cast<__nv_bfloat162*>(&Olo[(size_t)m * NOUT + n]) = __nv_bfloat162{l0, l1};
                }
            }
        }
}

// ---------------------------------------------------------------------------
// Launch
// ---------------------------------------------------------------------------
extern "C" void kernel_launch(void* const* d_in, const int* in_sizes, int n_in,
                              void* d_out, int out_size)
{
    const float* f1  = (const float*)d_in[0];
    const float* f2  = (const float*)d_in[1];
    const float* lat = (const float*)d_in[2];
    const float* g0w = (const float*)d_in[3];
    const float* g0b = (const float*)d_in[4];
    const float* g1w = (const float*)d_in[5];
    const float* g1b = (const float*)d_in[6];
    const float* g2w = (const float*)d_in[7];
    const float* g2b = (const float*)d_in[8];
    const float* W1  = (const float*)d_in[9];
    const float* b1  = (const float*)d_in[10];
    const float* W2  = (const float*)d_in[11];
    const float* b2  = (const float*)d_in[12];
    const float* W3  = (const float*)d_in[13];
    const float* b3  = (const float*)d_in[14];
    const float* W4  = (const float*)d_in[15];
    const float* b4  = (const float*)d_in[16];

    float* out      = (float*)d_out;
    float* gate_out = out + (size_t)B_ROWS * LATD;

    __nv_bfloat16 *w1hi, *w1lo, *w2hi, *w2lo, *w3hi, *w3lo, *w4hi, *w4lo;
    __nv_bfloat16 *xhi, *xlo, *h1hi, *h1lo, *h2hi, *h2lo;
    cudaGetSymbolAddress((void**)&w1hi, g_w1hi); cudaGetSymbolAddress((void**)&w1lo, g_w1lo);
    cudaGetSymbolAddress((void**)&w2hi, g_w2hi); cudaGetSymbolAddress((void**)&w2lo, g_w2lo);
    cudaGetSymbolAddress((void**)&w3hi, g_w3hi); cudaGetSymbolAddress((void**)&w3lo, g_w3lo);
    cudaGetSymbolAddress((void**)&w4hi, g_w4hi); cudaGetSymbolAddress((void**)&w4lo, g_w4lo);
    cudaGetSymbolAddress((void**)&xhi,  g_xhi);  cudaGetSymbolAddress((void**)&xlo,  g_xlo);
    cudaGetSymbolAddress((void**)&h1hi, g_h1hi); cudaGetSymbolAddress((void**)&h1lo, g_h1lo);
    cudaGetSymbolAddress((void**)&h2hi, g_h2hi); cudaGetSymbolAddress((void**)&h2lo, g_h2lo);

    // conversions
    {
        int n4 = NE * HID * NIN / 4;
        convert_hilo<<<(n4 + 255) / 256, 256>>>(W1, w1hi, w1lo, n4);
        n4 = NE * HID * HID / 4;
        convert_hilo<<<(n4 + 255) / 256, 256>>>(W2, w2hi, w2lo, n4);
        convert_hilo<<<(n4 + 255) / 256, 256>>>(W3, w3hi, w3lo, n4);
        n4 = NE * LATD * HID / 4;
        convert_hilo<<<(n4 + 255) / 256, 256>>>(W4, w4hi, w4lo, n4);
        int nx = B_ROWS * (NIN / 4);
        xprep_kernel<<<nx / 256, 256>>>(f1, f2, lat);
    }

    // gate path
    gate0_kernel<<<B_ROWS / 256, 256>>>(f1, f2, lat, g0w, g0b);
    gate1_kernel<<<B_ROWS / 256, 256>>>(g1w, g1b, g2w, g2b, gate_out);

    // blend layers — dynamic smem (2 stages of 92160B)
    constexpr int SMEM_BYTES = 2 * STAGE_U * 2;   // 184320

    cudaFuncSetAttribute(blend_mma<NIN, HID, true, false>,
                         cudaFuncAttributeMaxDynamicSharedMemorySize, SMEM_BYTES);
    cudaFuncSetAttribute(blend_mma<HID, HID, true, false>,
                         cudaFuncAttributeMaxDynamicSharedMemorySize, SMEM_BYTES);
    cudaFuncSetAttribute(blend_mma<HID, LATD, false, true>,
                         cudaFuncAttributeMaxDynamicSharedMemorySize, SMEM_BYTES);

    dim3 grid1(HID / 64, B_ROWS / 128);
    blend_mma<NIN, HID, true, false><<<grid1, 256, SMEM_BYTES>>>(
        xhi, xlo, w1hi, w1lo, b1, h1hi, h1lo, nullptr);
    blend_mma<HID, HID, true, false><<<grid1, 256, SMEM_BYTES>>>(
        h1hi, h1lo, w2hi, w2lo, b2, h2hi, h2lo, nullptr);
    blend_mma<HID, HID, true, false><<<grid1, 256, SMEM_BYTES>>>(
        h2hi, h2lo, w3hi, w3lo, b3, h1hi, h1lo, nullptr);

    dim3 grid4(LATD / 64, B_ROWS / 128);
    blend_mma<HID, LATD, false, true><<<grid4, 256, SMEM_BYTES>>>(
        h1hi, h1lo, w4hi, w4lo, b4, nullptr, nullptr, out);
}